// round 12
// baseline (speedup 1.0000x reference)
#include <cuda_runtime.h>
#include <cstdint>
#include <cstddef>

#define BN   16384          // batch
#define TT   10             // timesteps
#define II   184            // input features
#define HH   128            // hidden
#define G4   512            // 4*H (gate width)
#define BT   (BN * TT)      // 163840 rows
#define KP1  192            // padded K for layer-1 xproj

// ---------------- scratch (device globals; allocation-free) ----------------
__device__ float g_xp_f[(size_t)BT * G4];
__device__ float g_xp_b[(size_t)BT * G4];
__device__ float g_out1[(size_t)BT * 256];
__device__ float g_out2[(size_t)BT * 256];
__device__ float g_xr[(size_t)BT * KP1];     // tf32-rounded, padded x
__device__ float g_wr[4][512 * 256];         // rounded, padded w_ih (f,b,f2,b2)

// ---------------- helpers ----------------
__device__ __forceinline__ float sigm(float x) {
    return 1.0f / (1.0f + __expf(-x));
}
__device__ __forceinline__ float tf32r(float x) {
    uint32_t r;
    asm("cvt.rna.tf32.f32 %0, %1;" : "=r"(r) : "f"(x));
    return __uint_as_float(r);
}
__device__ __forceinline__ void mma8(float c[4], const uint32_t a[4],
                                     const uint32_t b[2]) {
    asm volatile(
        "mma.sync.aligned.m16n8k8.row.col.f32.tf32.tf32.f32 "
        "{%0,%1,%2,%3}, {%4,%5,%6,%7}, {%8,%9}, {%0,%1,%2,%3};"
        : "+f"(c[0]), "+f"(c[1]), "+f"(c[2]), "+f"(c[3])
        : "r"(a[0]), "r"(a[1]), "r"(a[2]), "r"(a[3]), "r"(b[0]), "r"(b[1]));
}
#define FU __float_as_uint

__device__ __forceinline__ uint32_t smem_u32(const void* p) {
    uint32_t a;
    asm("{ .reg .u64 t; cvta.to.shared.u64 t, %1; cvt.u32.u64 %0, t; }"
        : "=r"(a) : "l"(p));
    return a;
}
__device__ __forceinline__ void st_peer(uint32_t local_addr, uint32_t peer_rank,
                                        float v) {
    uint32_t pa;
    asm volatile("mapa.shared::cluster.u32 %0, %1, %2;"
                 : "=r"(pa) : "r"(local_addr), "r"(peer_rank));
    asm volatile("st.shared::cluster.f32 [%0], %1;" :: "r"(pa), "f"(v)
                 : "memory");
}

// ============================================================================
// Pre-round pass: dst[row][0..KP) = tf32_rna(src[row][0..K)), zero-padded.
// ============================================================================
__global__ void round_pad(const float* __restrict__ src, float* __restrict__ dst,
                          int K, int KPp, long long total4)
{
    const long long i4 = (long long)blockIdx.x * blockDim.x + threadIdx.x;
    if (i4 >= total4) return;
    const int kp4 = KPp >> 2;
    const long long row = i4 / kp4;
    const int c = (int)(i4 % kp4) * 4;
    float4 v = make_float4(0.f, 0.f, 0.f, 0.f);
    if (c < K) v = *(const float4*)(src + row * K + c);
    float4 o = make_float4(tf32r(v.x), tf32r(v.y), tf32r(v.z), tf32r(v.w));
    *(float4*)(dst + row * KPp + c) = o;
}

// ============================================================================
// xproj GEMM v3 (unchanged from R11, proven): cp.async + ldmatrix tf32 MMA.
// ============================================================================
#define XST      20480                 // stage bytes: A 128*80 + B 128*80
#define XP_SMEM  (3 * XST)             // 61440

__global__ __launch_bounds__(128, 2)
void xproj_mma(const float* __restrict__ A, const float* __restrict__ W,
               const float* __restrict__ bih, const float* __restrict__ bhh,
               float* __restrict__ C, int KPp)
{
    extern __shared__ char sx[];
    const uint32_t smb = smem_u32(sx);
    const int tid = threadIdx.x, l = tid & 31, w = tid >> 5;
    const int gid = l >> 2, tig = l & 3;
    const int nt = blockIdx.x, mt = blockIdx.y;
    const int warpm = w >> 1, warpn = w & 1;
    const int nblk = KPp >> 4;

    const float* Ag = A + (size_t)mt * 128 * KPp;
    const float* Wg = W + (size_t)nt * 128 * KPp;

    const int ckg = tid & 3, crw = tid >> 2;

    auto issue = [&](int c) {
        const uint32_t sA = smb + (c % 3) * XST;
        const uint32_t sB = sA + 10240;
        const float* ga = Ag + c * 16 + ckg * 4;
        const float* gb = Wg + c * 16 + ckg * 4;
#pragma unroll
        for (int i = 0; i < 4; i++) {
            const int r = crw + i * 32;
            asm volatile("cp.async.cg.shared.global [%0], [%1], 16;"
                         :: "r"(sA + r * 80 + ckg * 16),
                            "l"(ga + (size_t)r * KPp) : "memory");
            asm volatile("cp.async.cg.shared.global [%0], [%1], 16;"
                         :: "r"(sB + r * 80 + ckg * 16),
                            "l"(gb + (size_t)r * KPp) : "memory");
        }
    };

    const int lj = l >> 3, li = l & 7;
    const uint32_t offA = (uint32_t)((warpm * 64 + (lj & 1) * 8 + li) * 80
                                     + (lj >> 1) * 16);
    const uint32_t offB = (uint32_t)(10240 + (warpn * 64 + (lj >> 1) * 8 + li) * 80
                                     + (lj & 1) * 16);

    float acc[4][8][4];
#pragma unroll
    for (int m2 = 0; m2 < 4; m2++)
#pragma unroll
        for (int nn = 0; nn < 8; nn++)
#pragma unroll
            for (int r = 0; r < 4; r++) acc[m2][nn][r] = 0.0f;

    issue(0); asm volatile("cp.async.commit_group;" ::: "memory");
    issue(1); asm volatile("cp.async.commit_group;" ::: "memory");
    issue(2); asm volatile("cp.async.commit_group;" ::: "memory");

    for (int c = 0; c < nblk; c++) {
        asm volatile("cp.async.wait_group 2;" ::: "memory");
        __syncthreads();
        const uint32_t stg = smb + (c % 3) * XST;
#pragma unroll
        for (int kk = 0; kk < 2; kk++) {
            uint32_t a[4][4], b[4][4];
#pragma unroll
            for (int m2 = 0; m2 < 4; m2++)
                asm volatile(
                    "ldmatrix.sync.aligned.m8n8.x4.shared.b16 {%0,%1,%2,%3}, [%4];"
                    : "=r"(a[m2][0]), "=r"(a[m2][1]),
                      "=r"(a[m2][2]), "=r"(a[m2][3])
                    : "r"(stg + offA + m2 * 1280 + kk * 32));
#pragma unroll
            for (int n2 = 0; n2 < 4; n2++)
                asm volatile(
                    "ldmatrix.sync.aligned.m8n8.x4.shared.b16 {%0,%1,%2,%3}, [%4];"
                    : "=r"(b[n2][0]), "=r"(b[n2][1]),
                      "=r"(b[n2][2]), "=r"(b[n2][3])
                    : "r"(stg + offB + n2 * 1280 + kk * 32));
#pragma unroll
            for (int m2 = 0; m2 < 4; m2++)
#pragma unroll
                for (int n2 = 0; n2 < 4; n2++) {
                    mma8(acc[m2][n2 * 2],     a[m2], &b[n2][0]);
                    mma8(acc[m2][n2 * 2 + 1], a[m2], &b[n2][2]);
                }
        }
        __syncthreads();
        if (c + 3 < nblk) issue(c + 3);
        asm volatile("cp.async.commit_group;" ::: "memory");  // empty ok
    }

#pragma unroll
    for (int m2 = 0; m2 < 4; m2++) {
        const int row = mt * 128 + warpm * 64 + m2 * 16 + gid;
#pragma unroll
        for (int nn = 0; nn < 8; nn++) {
            const int col = nt * 128 + warpn * 64 + nn * 8 + tig * 2;
            const float b0 = bih[col] + bhh[col];
            const float b1 = bih[col + 1] + bhh[col + 1];
            *(float2*)(C + (size_t)row * G4 + col) =
                make_float2(acc[m2][nn][0] + b0, acc[m2][nn][1] + b1);
            *(float2*)(C + (size_t)(row + 8) * G4 + col) =
                make_float2(acc[m2][nn][2] + b0, acc[m2][nn][3] + b1);
        }
    }
}

// ============================================================================
// Persistent LSTM layer v3: Whh in REGISTERS, h-plane only in smem.
// 256 threads / 8 warps; warp = all 64 rows (4 m16) x 4 gate-n8 tiles for its
// 8 j-columns. Whh fragments [4 gates][16 kk][2] = 128 regs/thread, loaded
// once per layer. Per-step smem traffic = A (h) fragments only.
// Cluster-2 exchanges h halves via DSMEM; split arrive/wait protects the
// h-plane overwrite (reads-done) and publication (writes-done).
// ============================================================================
#define A_F2S  68                              // A row stride in float2
#define A_FLOATS (64 * A_F2S * 2)              // 8704
#define L_SMEM  (A_FLOATS * 4)                 // 34816 bytes

__global__ __launch_bounds__(256, 1) __cluster_dims__(2, 1, 1)
void lstm_layer(const float* __restrict__ whh_f, const float* __restrict__ whh_b,
                const float* __restrict__ xpf, const float* __restrict__ xpb,
                float* __restrict__ outbuf, int round_out)
{
    extern __shared__ float sl[];
    float*  Afl = sl;
    float2* A2  = (float2*)sl;

    uint32_t q;
    asm("mov.u32 %0, %%cluster_ctarank;" : "=r"(q));
    const uint32_t peer = q ^ 1u;
    const int rowblk = blockIdx.x >> 1;
    const int dir = blockIdx.y;
    const int row0 = rowblk * 64;
    const float* xp  = dir ? xpb : xpf;
    const float* whh = dir ? whh_b : whh_f;

    const int tid = threadIdx.x, l = tid & 31, w = tid >> 5;   // w = warpj 0..7
    const int gid = l >> 2, tig = l & 3;

    // ---- load resident Whh fragments into registers (once per layer) ----
    // B frag for gate g, chunk kk: Whh[g*128 + q*64 + w*8 + gid][kk*8 + tig(+4)]
    uint32_t Bw[4][16][2];
    {
        const int nrow = (int)q * 64 + w * 8 + gid;
#pragma unroll
        for (int g = 0; g < 4; g++) {
            const float* src = whh + (size_t)(g * 128 + nrow) * HH + tig;
#pragma unroll
            for (int kk = 0; kk < 16; kk++) {
                Bw[g][kk][0] = FU(tf32r(src[kk * 8]));
                Bw[g][kk][1] = FU(tf32r(src[kk * 8 + 4]));
            }
        }
    }

    // per-thread fixed coordinates
    const int jl2 = w * 8 + tig * 2;              // local j pair
    const int jg  = (int)q * 64 + jl2;            // global hidden col
    const int pA  = (jg >> 3) * 4 + (jg & 3);     // A pair index for h writes
    const int sA  = (jg >> 2) & 1;                // slot (same for jg and jg+1)

    float2 cc[8];                                 // cell state (8 rows x 2 cols)

    for (int ti = 0; ti < TT; ti++) {
        const int t = dir ? (TT - 1 - ti) : ti;

        float acc[4][4][4];
#pragma unroll
        for (int mt = 0; mt < 4; mt++)
#pragma unroll
            for (int g = 0; g < 4; g++)
#pragma unroll
                for (int r = 0; r < 4; r++) acc[mt][g][r] = 0.0f;

        if (ti > 0) {
#pragma unroll
            for (int kk = 0; kk < 16; kk++) {
                const int p = kk * 4 + tig;
                float2 fa[8];
#pragma unroll
                for (int i = 0; i < 8; i++)
                    fa[i] = A2[(gid + 8 * i) * A_F2S + p];
#pragma unroll
                for (int mt = 0; mt < 4; mt++) {
                    const uint32_t a[4] = {FU(fa[2 * mt].x), FU(fa[2 * mt + 1].x),
                                           FU(fa[2 * mt].y), FU(fa[2 * mt + 1].y)};
#pragma unroll
                    for (int g = 0; g < 4; g++)
                        mma8(acc[mt][g], a, Bw[g][kk]);
                }
            }
        }
        __syncthreads();                              // CTA-local reads done
        asm volatile("barrier.cluster.arrive.aligned;" ::: "memory"); // reads-done

        // ---- cell math into registers (no smem writes yet) ----
        float2 hv[8];
#pragma unroll
        for (int i = 0; i < 8; i++) {
            const int mt = i >> 1, rh = i & 1, e = rh * 2;
            const int brow = row0 + gid + 8 * i;
            const float* xpr = xp + ((size_t)brow * TT + t) * G4 + jg;
            float2 xi = *(const float2*)(xpr + 0 * HH);
            float2 xf = *(const float2*)(xpr + 1 * HH);
            float2 xg = *(const float2*)(xpr + 2 * HH);
            float2 xo = *(const float2*)(xpr + 3 * HH);

            float i0 = sigm(acc[mt][0][e]     + xi.x);
            float i1 = sigm(acc[mt][0][e + 1] + xi.y);
            float f0 = sigm(acc[mt][1][e]     + xf.x);
            float f1 = sigm(acc[mt][1][e + 1] + xf.y);
            float g0 = tanhf(acc[mt][2][e]     + xg.x);
            float g1 = tanhf(acc[mt][2][e + 1] + xg.y);
            float o0 = sigm(acc[mt][3][e]     + xo.x);
            float o1 = sigm(acc[mt][3][e + 1] + xo.y);

            float2 cp = (ti > 0) ? cc[i] : make_float2(0.f, 0.f);
            float2 cn = make_float2(f0 * cp.x + i0 * g0, f1 * cp.y + i1 * g1);
            hv[i] = make_float2(o0 * tanhf(cn.x), o1 * tanhf(cn.y));
            cc[i] = cn;
        }

        asm volatile("barrier.cluster.wait.aligned;" ::: "memory"); // peer reads done

        // ---- publish h: outbuf + both CTAs' A planes ----
#pragma unroll
        for (int i = 0; i < 8; i++) {
            const int lr = gid + 8 * i;
            const int brow = row0 + lr;
            const float h0 = tf32r(hv[i].x), h1 = tf32r(hv[i].y);
            const float2 hw = round_out ? make_float2(h0, h1) : hv[i];
            *(float2*)(outbuf + ((size_t)brow * TT + t) * 256 + dir * HH + jg) = hw;

            float* dst = &Afl[lr * (A_F2S * 2) + pA * 2 + sA];
            dst[0] = h0;
            dst[2] = h1;                         // pair pA+1, same slot
            const uint32_t da = smem_u32(dst);
            st_peer(da,     peer, h0);
            st_peer(da + 8, peer, h1);
        }
        __syncthreads();
        asm volatile("barrier.cluster.arrive.aligned;" ::: "memory"); // writes-done
        asm volatile("barrier.cluster.wait.aligned;"   ::: "memory");
    }
}

// ============================================================================
// Max-pool + fc1(relu) + fc2, fused. (unchanged, proven)
// ============================================================================
__global__ void fc_head(const float* __restrict__ out2,
                        const float* __restrict__ w1, const float* __restrict__ b1,
                        const float* __restrict__ w2, const float* __restrict__ b2,
                        float* __restrict__ y)
{
    extern __shared__ float smf[];
    float* wfc = smf;
    float* v   = wfc + 64 * 513;
    float* red = v + 512;
    const int tid = threadIdx.x;

    for (int i = tid; i < 64 * 512; i += 512)
        wfc[(i >> 9) * 513 + (i & 511)] = w1[i];
    __syncthreads();

    const int jj = tid & 63, part = tid >> 6;

    for (int rr = 0; rr < 32; rr++) {
        const int b = blockIdx.x * 32 + rr;
        {
            int c = tid >> 1, p = tid & 1;
            const float* p0 = out2 + ((size_t)b * TT + p * 5) * 256 + c;
            float mx = p0[0];
            mx = fmaxf(mx, p0[256]);  mx = fmaxf(mx, p0[512]);
            mx = fmaxf(mx, p0[768]);  mx = fmaxf(mx, p0[1024]);
            v[tid] = mx;
        }
        __syncthreads();

        float s = 0.0f;
        const float* wr = wfc + jj * 513 + part * 64;
        const float* vr = v + part * 64;
#pragma unroll
        for (int i = 0; i < 64; i++) s += wr[i] * vr[i];
        red[tid] = s;
        __syncthreads();

        if (tid < 64) {
            float h = red[tid]       + red[64 + tid]  + red[128 + tid] +
                      red[192 + tid] + red[256 + tid] + red[320 + tid] +
                      red[384 + tid] + red[448 + tid] + b1[tid];
            h = fmaxf(h, 0.0f);
            red[tid] = h * w2[tid];
        }
        __syncthreads();

        if (tid == 0) {
            float s2 = b2[0];
#pragma unroll
            for (int j2 = 0; j2 < 64; j2++) s2 += red[j2];
            y[b] = s2;
        }
        __syncthreads();
    }
}

// ============================================================================
extern "C" void kernel_launch(void* const* d_in, const int* in_sizes, int n_in,
                              void* d_out, int out_size)
{
    (void)in_sizes; (void)n_in; (void)out_size;
    const float* x     = (const float*)d_in[0];
    const float* wih1f = (const float*)d_in[1];
    const float* whh1f = (const float*)d_in[2];
    const float* bih1f = (const float*)d_in[3];
    const float* bhh1f = (const float*)d_in[4];
    const float* wih1b = (const float*)d_in[5];
    const float* whh1b = (const float*)d_in[6];
    const float* bih1b = (const float*)d_in[7];
    const float* bhh1b = (const float*)d_in[8];
    const float* wih2f = (const float*)d_in[9];
    const float* whh2f = (const float*)d_in[10];
    const float* bih2f = (const float*)d_in[11];
    const float* bhh2f = (const float*)d_in[12];
    const float* wih2b = (const float*)d_in[13];
    const float* whh2b = (const float*)d_in[14];
    const float* bih2b = (const float*)d_in[15];
    const float* bhh2b = (const float*)d_in[16];
    const float* fc1w  = (const float*)d_in[17];
    const float* fc1b  = (const float*)d_in[18];
    const float* fc2w  = (const float*)d_in[19];
    const float* fc2b  = (const float*)d_in[20];
    float* y = (float*)d_out;

    float *xpf, *xpb, *o1, *o2, *xr, *wrb;
    cudaGetSymbolAddress((void**)&xpf, g_xp_f);
    cudaGetSymbolAddress((void**)&xpb, g_xp_b);
    cudaGetSymbolAddress((void**)&o1,  g_out1);
    cudaGetSymbolAddress((void**)&o2,  g_out2);
    cudaGetSymbolAddress((void**)&xr,  g_xr);
    cudaGetSymbolAddress((void**)&wrb, g_wr);
    float* wr1f = wrb + 0 * 512 * 256;
    float* wr1b = wrb + 1 * 512 * 256;
    float* wr2f = wrb + 2 * 512 * 256;
    float* wr2b = wrb + 3 * 512 * 256;

    cudaFuncSetAttribute(xproj_mma, cudaFuncAttributeMaxDynamicSharedMemorySize,
                         (int)XP_SMEM);
    cudaFuncSetAttribute(lstm_layer, cudaFuncAttributeMaxDynamicSharedMemorySize,
                         (int)L_SMEM);

    const dim3 xgrid(4, BT / 128);       // nt fastest -> A-tile L2 reuse
    const dim3 lgrid(2 * (BN / 64), 2);  // (2 cluster CTAs x 256 blks) x 2 dir

    // ---- pre-round passes ----
    const long long t4x = (long long)BT * (KP1 / 4);
    round_pad<<<(unsigned)((t4x + 255) / 256), 256>>>(x, xr, II, KP1, t4x);
    round_pad<<<(512 * 48 + 255) / 256, 256>>>(wih1f, wr1f, II, KP1, 512 * 48);
    round_pad<<<(512 * 48 + 255) / 256, 256>>>(wih1b, wr1b, II, KP1, 512 * 48);
    round_pad<<<(512 * 64 + 255) / 256, 256>>>(wih2f, wr2f, 256, 256, 512 * 64);
    round_pad<<<(512 * 64 + 255) / 256, 256>>>(wih2b, wr2b, 256, 256, 512 * 64);

    // ---- layer 1 ----
    xproj_mma<<<xgrid, 128, XP_SMEM>>>(xr, wr1f, bih1f, bhh1f, xpf, KP1);
    xproj_mma<<<xgrid, 128, XP_SMEM>>>(xr, wr1b, bih1b, bhh1b, xpb, KP1);
    lstm_layer<<<lgrid, 256, L_SMEM>>>(whh1f, whh1b, xpf, xpb, o1, 1);

    // ---- layer 2 (o1 already tf32-rounded at write) ----
    xproj_mma<<<xgrid, 128, XP_SMEM>>>(o1, wr2f, bih2f, bhh2f, xpf, 256);
    xproj_mma<<<xgrid, 128, XP_SMEM>>>(o1, wr2b, bih2b, bhh2b, xpb, 256);
    lstm_layer<<<lgrid, 256, L_SMEM>>>(whh2f, whh2b, xpf, xpb, o2, 0);

    // ---- pool + FC head ----
    cudaFuncSetAttribute(fc_head, cudaFuncAttributeMaxDynamicSharedMemorySize,
                         (64 * 513 + 512 + 512) * (int)sizeof(float));
    fc_head<<<BN / 32, 512, (64 * 513 + 512 + 512) * sizeof(float)>>>(
        o2, fc1w, fc1b, fc2w, fc2b, y);
}